// round 4
// baseline (speedup 1.0000x reference)
#include <cuda_runtime.h>
#include <cuda_bf16.h>

#define FULL 0xffffffffu

namespace {
constexpr int NB   = 32;
constexpr int NP   = 32;
constexpr int DD   = 12;
constexpr int PP   = 32;
constexpr int LL   = 1024;
constexpr int LOUT = 32;
constexpr int CPL  = 8;            // cols per lane
constexpr int WBLK = 32 * CPL;     // 256 cols per warp
constexpr int NBLK = LL / WBLK;    // 4 warps per (b,n)
constexpr float BIGV = 1e30f;
}

// One CTA (4 warps) per (b, n); warp w owns column block w. Warps run a
// decoupled pipeline: the only cross-warp value per row is the last-column
// carry D[i][j0-1], passed as a tagged 64-bit word {tag=i+1, value} through
// volatile smem (single-word atomicity => no barrier, no fence). Warp w spins
// only if warp w-1 hasn't finished row i yet; steady-state skew is 1 row.
// Row math (w == 1 since RHO = 1.0):
//   cur[j] = S[j] + min_{k<=j}( m[k] - S[k-1] ),  m[j] = min(D[i-1,j-1], D[i-1,j])
// The cost+sum-scan of row i+1 is computed in the same iteration as the DP
// min-scan of row i so the two dependency chains interleave.
__global__ void __launch_bounds__(128, 3)
dtw_fused_kernel(const float* __restrict__ x,
                 const float* __restrict__ patts,
                 float* __restrict__ out)
{
    const int gid  = blockIdx.x;        // 0..1023
    const int b    = gid >> 5;
    const int n    = gid & 31;
    const int w    = threadIdx.x >> 5;  // column block 0..3
    const int lane = threadIdx.x & 31;

    __shared__ unsigned long long carry[NBLK - 1][PP];  // {tag=i+1 | bits(val)}

    // init tags to 0 (never matches any i+1 >= 1)
    for (int idx = threadIdx.x; idx < (NBLK - 1) * PP; idx += 128)
        ((unsigned long long*)carry)[idx] = 0ull;
    __syncthreads();

    // lane holds patts[n][d][lane]; store -2*p for the FMA form of sqdist.
    float prow[DD];
    float p2 = 0.0f;
    {
        const float* pp = patts + n * (DD * PP) + lane;
        #pragma unroll
        for (int d = 0; d < DD; ++d) {
            float v = pp[d * PP];
            p2 = fmaf(v, v, p2);
            prow[d] = -2.0f * v;
        }
    }

    // x chunk for this warp's column block, reused by all 32 rows.
    const float* xb = x + b * (DD * LL);
    const int j0 = w * WBLK;
    float xr[DD][CPL];
    float x2[CPL] = {0.f, 0.f, 0.f, 0.f, 0.f, 0.f, 0.f, 0.f};
    #pragma unroll
    for (int d = 0; d < DD; ++d) {
        const float* px = xb + d * LL + j0 + CPL * lane;
        float4 v0 = *reinterpret_cast<const float4*>(px);
        float4 v1 = *reinterpret_cast<const float4*>(px + 4);
        xr[d][0] = v0.x; xr[d][1] = v0.y; xr[d][2] = v0.z; xr[d][3] = v0.w;
        xr[d][4] = v1.x; xr[d][5] = v1.y; xr[d][6] = v1.z; xr[d][7] = v1.w;
        #pragma unroll
        for (int k = 0; k < CPL; ++k) x2[k] = fmaf(xr[d][k], xr[d][k], x2[k]);
    }

    float* outb = out + ((b * NP + n) * PP) * LOUT;

    // cost row i + local inclusive prefix + warp-exclusive sum
    auto costscan = [&](int i, float s[CPL], float& excl) {
        float p2b = __shfl_sync(FULL, p2, i);
        float c[CPL];
        #pragma unroll
        for (int k = 0; k < CPL; ++k) c[k] = p2b + x2[k];
        #pragma unroll
        for (int d = 0; d < DD; ++d) {
            float pb = __shfl_sync(FULL, prow[d], i);
            #pragma unroll
            for (int k = 0; k < CPL; ++k) c[k] = fmaf(pb, xr[d][k], c[k]);
        }
        s[0] = c[0];
        #pragma unroll
        for (int k = 1; k < CPL; ++k) s[k] = s[k - 1] + c[k];
        float tot = s[CPL - 1];
        #pragma unroll
        for (int o = 1; o < 32; o <<= 1) {
            float u = __shfl_up_sync(FULL, tot, o);
            if (lane >= o) tot += u;
        }
        excl = tot - s[CPL - 1];
    };

    float Dp[CPL];          // previous DP row for this warp's block
    float bm = BIGV;        // D[i-1][j0-1] == previous iteration's bl
    float sC[CPL], eC;
    costscan(0, sC, eC);

    #pragma unroll 1
    for (int i = 0; i < PP; ++i) {
        // ---- pipelined: next row's cost + sum-scan (independent of DP chain) ----
        float sN[CPL], eN;
        if (i + 1 < PP) costscan(i + 1, sN, eN);

        // ---- left-boundary carry for this row ----
        float bl;
        if (w == 0) {
            bl = (i == 0) ? 0.0f : BIGV;   // D[0,0] seed; col -1 otherwise OOR
        } else {
            const unsigned tag = (unsigned)(i + 1);
            unsigned long long v = *(volatile unsigned long long*)&carry[w - 1][i];
            while ((unsigned)(v >> 32) != tag) {
                __nanosleep(20);
                v = *(volatile unsigned long long*)&carry[w - 1][i];
            }
            bl = __uint_as_float((unsigned)v);
        }

        // ---- t[k] = min(up-left, up) - S[j-1] ----
        float tt[CPL];
        float shin = __shfl_up_sync(FULL, Dp[CPL - 1], 1);
        if (i == 0) {
            #pragma unroll
            for (int k = 0; k < CPL; ++k) tt[k] = BIGV;
        } else {
            float mprev = (lane == 0) ? bm : shin;
            tt[0] = fminf(mprev, Dp[0]) - eC;
            #pragma unroll
            for (int k = 1; k < CPL; ++k)
                tt[k] = fminf(Dp[k - 1], Dp[k]) - (eC + sC[k - 1]);
        }

        // ---- prefix-min with left-entry bl injected at position -1 ----
        float q[CPL];
        q[0] = (lane == 0) ? fminf(bl, tt[0]) : tt[0];
        #pragma unroll
        for (int k = 1; k < CPL; ++k) q[k] = fminf(q[k - 1], tt[k]);

        float mt = q[CPL - 1];
        #pragma unroll
        for (int o = 1; o < 32; o <<= 1)
            mt = fminf(mt, __shfl_up_sync(FULL, mt, o));  // OOR self-min: no-op
        float eprev = __shfl_up_sync(FULL, mt, 1);
        if (lane == 0) eprev = BIGV;

        float cur[CPL];
        #pragma unroll
        for (int k = 0; k < CPL; ++k)
            cur[k] = (eC + sC[k]) + fminf(eprev, q[k]);

        // ---- publish carry for the warp to the right ----
        if (w < NBLK - 1 && lane == 31) {
            unsigned long long pk =
                (((unsigned long long)(unsigned)(i + 1)) << 32) |
                (unsigned long long)__float_as_uint(cur[CPL - 1]);
            *(volatile unsigned long long*)&carry[w][i] = pk;
        }

        // ---- output: cols 992..1023 = lanes 28..31 of last warp ----
        if (w == NBLK - 1 && lane >= 28) {
            float* po = outb + i * LOUT + (lane - 28) * CPL;
            *reinterpret_cast<float4*>(po)     = make_float4(cur[0], cur[1], cur[2], cur[3]);
            *reinterpret_cast<float4*>(po + 4) = make_float4(cur[4], cur[5], cur[6], cur[7]);
        }

        bm = bl;
        #pragma unroll
        for (int k = 0; k < CPL; ++k) Dp[k] = cur[k];
        #pragma unroll
        for (int k = 0; k < CPL; ++k) sC[k] = sN[k];
        eC = eN;
    }
}

extern "C" void kernel_launch(void* const* d_in, const int* in_sizes, int n_in,
                              void* d_out, int out_size) {
    const float* x     = (const float*)d_in[0];   // [32, 12, 1024]
    const float* patts = (const float*)d_in[1];   // [32, 12, 32]
    float* out = (float*)d_out;                   // [32, 32, 32, 32]
    (void)in_sizes; (void)n_in; (void)out_size;
    dtw_fused_kernel<<<NB * NP, 128>>>(x, patts, out);
}